// round 1
// baseline (speedup 1.0000x reference)
#include <cuda_runtime.h>
#include <cuda_bf16.h>
#include <math.h>

// ReDrafter head: B=64, H=4096, D=512, V=32000, K=4 steps.
// fp32 baseline: tiled 64x64x32 shared-memory GEMM (4x4 microtiles),
// split-K partials for the small GEMMs, fused argmax+embed-gather.

#define B_ 64
#define D_ 512
#define H_ 4096
#define V_ 32000
#define G3 1536           // 3*D
#define LDOUT 128000L     // K*V per batch row in output [B,K,V]

// ---------------- scratch (device globals; no allocation allowed) ----------
__device__ float g_part[8 * B_ * D_];        // in_proj split-K partials [8][64][512]
__device__ float g_gP[2 * B_ * 2 * G3];      // GRU gate partials [2 splits][64][3072]
__device__ float g_h0[B_ * D_];
__device__ float g_h1[B_ * D_];
__device__ float g_x[B_ * D_];

// ---------------- 64x64 output tile GEMM: C[b,n] = sum_k A[b,k]*W[n,k] -----
// A: 64 rows, lda. Wt: pre-offset to this tile's first row, ldw.
// Ct: pre-offset to this tile's first column, row stride ldc.
__device__ __forceinline__ void gemm_tile_64(
    const float* __restrict__ A, int lda,
    const float* __restrict__ Wt, int ldw,
    float* __restrict__ Ct, long ldc,
    int k0, int klen)
{
    __shared__ __align__(16) float As[32][68];
    __shared__ __align__(16) float Ws[32][68];

    const int t  = threadIdx.x;      // 256 threads
    const int tx = t & 15;
    const int ty = t >> 4;

    float acc[4][4];
#pragma unroll
    for (int i = 0; i < 4; i++)
#pragma unroll
        for (int j = 0; j < 4; j++) acc[i][j] = 0.f;

    for (int kb = k0; kb < k0 + klen; kb += 32) {
#pragma unroll
        for (int i = 0; i < 8; i++) {
            int idx = t + i * 256;
            int r = idx >> 5;        // 0..63
            int k = idx & 31;        // 0..31
            As[k][r] = A[(long)r * lda + kb + k];
            Ws[k][r] = Wt[(long)r * ldw + kb + k];
        }
        __syncthreads();
#pragma unroll
        for (int k = 0; k < 32; k++) {
            float4 av = *(const float4*)&As[k][ty << 2];
            float4 wv = *(const float4*)&Ws[k][tx << 2];
            acc[0][0] = fmaf(av.x, wv.x, acc[0][0]);
            acc[0][1] = fmaf(av.x, wv.y, acc[0][1]);
            acc[0][2] = fmaf(av.x, wv.z, acc[0][2]);
            acc[0][3] = fmaf(av.x, wv.w, acc[0][3]);
            acc[1][0] = fmaf(av.y, wv.x, acc[1][0]);
            acc[1][1] = fmaf(av.y, wv.y, acc[1][1]);
            acc[1][2] = fmaf(av.y, wv.z, acc[1][2]);
            acc[1][3] = fmaf(av.y, wv.w, acc[1][3]);
            acc[2][0] = fmaf(av.z, wv.x, acc[2][0]);
            acc[2][1] = fmaf(av.z, wv.y, acc[2][1]);
            acc[2][2] = fmaf(av.z, wv.z, acc[2][2]);
            acc[2][3] = fmaf(av.z, wv.w, acc[2][3]);
            acc[3][0] = fmaf(av.w, wv.x, acc[3][0]);
            acc[3][1] = fmaf(av.w, wv.y, acc[3][1]);
            acc[3][2] = fmaf(av.w, wv.z, acc[3][2]);
            acc[3][3] = fmaf(av.w, wv.w, acc[3][3]);
        }
        __syncthreads();
    }
#pragma unroll
    for (int i = 0; i < 4; i++) {
        int b = (ty << 2) + i;
        float* cr = Ct + (long)b * ldc + (tx << 2);
        *(float4*)cr = make_float4(acc[i][0], acc[i][1], acc[i][2], acc[i][3]);
    }
}

// ---------------- in-proj: h0 = hidden @ in_proj_w.T (split-K=8) -----------
__global__ void k_inproj_gemm(const float* __restrict__ H,
                              const float* __restrict__ W)
{
    int n0 = blockIdx.x * 64;       // 0..448 (8 tiles of D=512)
    int sp = blockIdx.y;            // 0..7, K chunk of 512
    gemm_tile_64(H, H_, W + (long)n0 * H_, H_,
                 g_part + (long)sp * (B_ * D_) + n0, D_,
                 sp * 512, 512);
}

__global__ void k_inproj_reduce(const float* __restrict__ bias)
{
    int id = blockIdx.x * 256 + threadIdx.x;   // < 32768
    int d = id & (D_ - 1);
    float s = bias[d];
#pragma unroll
    for (int sp = 0; sp < 8; sp++) s += g_part[sp * (B_ * D_) + id];
    g_h0[id] = s;
    g_h1[id] = s;
    g_x[id] = 0.f;
}

// ---------------- GRU gate GEMMs: virtual N=3072 (gi | gh), split-K=2 ------
// j in [0,1536): gi[b,j] = sum_k A1[b,k] * W1[j,k]
// j in [1536,3072): gh[b,j-1536] = sum_k A2[b,k] * W2[j-1536,k]
__global__ void k_gru_gemm(const float* __restrict__ A1, const float* __restrict__ W1,
                           const float* __restrict__ A2, const float* __restrict__ W2)
{
    int j0 = blockIdx.x * 64;       // 0..3008
    int sp = blockIdx.y;            // 0..1, K chunk of 256
    const float* A;
    const float* Wt;
    if (j0 < G3) { A = A1; Wt = W1 + (long)j0 * D_; }
    else         { A = A2; Wt = W2 + (long)(j0 - G3) * D_; }
    gemm_tile_64(A, D_, Wt, D_,
                 g_gP + (long)sp * (B_ * 2 * G3) + j0, 2 * G3,
                 sp * 256, 256);
}

// ---------------- GRU combine: gate nonlinearity + state update ------------
__global__ void k_gru_combine(const float* __restrict__ b_ih,
                              const float* __restrict__ b_hh,
                              float* __restrict__ h)
{
    int id = blockIdx.x * 256 + threadIdx.x;   // < 32768
    int b = id >> 9;
    int d = id & (D_ - 1);
    const float* p0 = g_gP + (long)b * (2 * G3);
    const float* p1 = g_gP + (long)(B_ * 2 * G3) + (long)b * (2 * G3);

    float gir = p0[d]        + p1[d]        + b_ih[d];
    float giz = p0[512 + d]  + p1[512 + d]  + b_ih[512 + d];
    float gin = p0[1024 + d] + p1[1024 + d] + b_ih[1024 + d];
    float ghr = p0[1536 + d] + p1[1536 + d] + b_hh[d];
    float ghz = p0[2048 + d] + p1[2048 + d] + b_hh[512 + d];
    float ghn = p0[2560 + d] + p1[2560 + d] + b_hh[1024 + d];

    float r = 1.f / (1.f + expf(-(gir + ghr)));
    float z = 1.f / (1.f + expf(-(giz + ghz)));
    float n = tanhf(gin + r * ghn);
    float hp = h[id];
    h[id] = n + z * (hp - n);     // (1-z)*n + z*h
}

// ---------------- logits: out[b,t,:] = h1 @ out_w.T ------------------------
__global__ void k_logits(const float* __restrict__ Wo,
                         float* __restrict__ out, int step)
{
    int n0 = blockIdx.x * 64;       // 500 tiles over V=32000
    gemm_tile_64(g_h1, D_, Wo + (long)n0 * D_, D_,
                 out + (long)step * V_ + n0, LDOUT,
                 0, 512);
}

// ---------------- argmax over V per batch row + embed gather → x -----------
__global__ void k_argmax(const float* __restrict__ logits,   // base + t*V
                         const float* __restrict__ embed)
{
    __shared__ float sv[256];
    __shared__ int   si[256];
    int b = blockIdx.x;
    int t = threadIdx.x;
    const float* row = logits + (long)b * LDOUT;
    float best = -3.4e38f;
    int bi = 0;
    for (int v = t; v < V_; v += 256) {
        float val = row[v];
        if (val > best) { best = val; bi = v; }   // strict > keeps lowest idx
    }
    sv[t] = best; si[t] = bi;
    __syncthreads();
    for (int s = 128; s > 0; s >>= 1) {
        if (t < s) {
            if (sv[t + s] > sv[t] || (sv[t + s] == sv[t] && si[t + s] < si[t])) {
                sv[t] = sv[t + s]; si[t] = si[t + s];
            }
        }
        __syncthreads();
    }
    int idx = si[0];
    const float4* e = (const float4*)(embed + (long)idx * D_);
    float4* xo = (float4*)(g_x + (long)b * D_);
    if (t < 128) xo[t] = e[t];
}

// ---------------- launch sequence ------------------------------------------
extern "C" void kernel_launch(void* const* d_in, const int* in_sizes, int n_in,
                              void* d_out, int out_size)
{
    const float* hid  = (const float*)d_in[0];
    const float* ipw  = (const float*)d_in[1];
    const float* ipb  = (const float*)d_in[2];
    const float* wih0 = (const float*)d_in[3];
    const float* whh0 = (const float*)d_in[4];
    const float* bih0 = (const float*)d_in[5];
    const float* bhh0 = (const float*)d_in[6];
    const float* wih1 = (const float*)d_in[7];
    const float* whh1 = (const float*)d_in[8];
    const float* bih1 = (const float*)d_in[9];
    const float* bhh1 = (const float*)d_in[10];
    const float* emb  = (const float*)d_in[11];
    const float* outw = (const float*)d_in[12];
    float* out = (float*)d_out;

    float *h0p, *h1p, *xp;
    cudaGetSymbolAddress((void**)&h0p, g_h0);
    cudaGetSymbolAddress((void**)&h1p, g_h1);
    cudaGetSymbolAddress((void**)&xp,  g_x);

    // h0 = hidden @ in_proj_w.T + b ; h_l0 = h_l1 = h0 ; x = 0
    k_inproj_gemm<<<dim3(8, 8), 256>>>(hid, ipw);
    k_inproj_reduce<<<128, 256>>>(ipb);

    for (int t = 0; t < 4; t++) {
        // layer 0: x -> h0
        k_gru_gemm<<<dim3(48, 2), 256>>>(xp, wih0, h0p, whh0);
        k_gru_combine<<<128, 256>>>(bih0, bhh0, h0p);
        // layer 1: h0 -> h1
        k_gru_gemm<<<dim3(48, 2), 256>>>(h0p, wih1, h1p, whh1);
        k_gru_combine<<<128, 256>>>(bih1, bhh1, h1p);
        // logits for this step
        k_logits<<<500, 256>>>(outw, out, t);
        // greedy token -> next x (skip after last step)
        if (t < 3) k_argmax<<<64, 256>>>(out + (long)t * V_, emb);
    }
}

// round 4
// speedup vs baseline: 1.7560x; 1.7560x over previous
#include <cuda_runtime.h>
#include <cuda_bf16.h>
#include <math.h>
#include <stdint.h>

// ReDrafter head via mma.sync bf16 (HMMA): B=64, D=512, H=4096, V=32000, K=4.
// Exact 2-way bf16 split of fp32 operands; 3 cross products accumulated fp32.

#define B_ 64
#define D_ 512
#define H_ 4096
#define V_ 32000
#define G3 1536
#define LDOUT 128000L

#define STAGE_BYTES 30720        // A0(5120)+A1(5120)+W0(10240)+W1(10240)
#define NSTAGE 3
#define DYN_SMEM (STAGE_BYTES * NSTAGE)

// ------------------------------ device scratch ------------------------------
__device__ __align__(128) __nv_bfloat16 g_wo0[V_ * D_],  g_wo1[V_ * D_];
__device__ __align__(128) __nv_bfloat16 g_wi00[G3 * D_], g_wi01[G3 * D_];
__device__ __align__(128) __nv_bfloat16 g_wh00[G3 * D_], g_wh01[G3 * D_];
__device__ __align__(128) __nv_bfloat16 g_wi10[G3 * D_], g_wi11[G3 * D_];
__device__ __align__(128) __nv_bfloat16 g_wh10[G3 * D_], g_wh11[G3 * D_];
__device__ __align__(128) __nv_bfloat16 g_ip0[D_ * H_],  g_ip1[D_ * H_];
__device__ __align__(128) __nv_bfloat16 g_hid0[B_ * H_], g_hid1[B_ * H_];
__device__ __align__(128) __nv_bfloat16 g_x0[B_ * D_],   g_x1[B_ * D_];
__device__ __align__(128) __nv_bfloat16 g_h00[B_ * D_],  g_h01[B_ * D_];
__device__ __align__(128) __nv_bfloat16 g_h10[B_ * D_],  g_h11[B_ * D_];
__device__ float g_h0f[B_ * D_];
__device__ float g_h1f[B_ * D_];
__device__ float g_ipart[8 * B_ * D_];
__device__ float g_gP[2 * B_ * 2 * G3];

// ------------------------------ helpers -------------------------------------
__device__ __forceinline__ uint32_t smem_u32(const void* p) {
    uint32_t a;
    asm("{ .reg .u64 t; cvta.to.shared.u64 t, %1; cvt.u32.u64 %0, t; }" : "=r"(a) : "l"(p));
    return a;
}
__device__ __forceinline__ void cp16(uint32_t dst, const void* src) {
    asm volatile("cp.async.cg.shared.global [%0], [%1], 16;" :: "r"(dst), "l"(src));
}
__device__ __forceinline__ void ldsm4(uint32_t* r, uint32_t a) {
    asm volatile("ldmatrix.sync.aligned.m8n8.x4.shared.b16 {%0,%1,%2,%3}, [%4];"
                 : "=r"(r[0]), "=r"(r[1]), "=r"(r[2]), "=r"(r[3]) : "r"(a));
}
__device__ __forceinline__ void mma16816(float* c, const uint32_t* a,
                                         uint32_t b0, uint32_t b1) {
    asm volatile(
        "mma.sync.aligned.m16n8k16.row.col.f32.bf16.bf16.f32 "
        "{%0,%1,%2,%3}, {%4,%5,%6,%7}, {%8,%9}, {%0,%1,%2,%3};"
        : "+f"(c[0]), "+f"(c[1]), "+f"(c[2]), "+f"(c[3])
        : "r"(a[0]), "r"(a[1]), "r"(a[2]), "r"(a[3]), "r"(b0), "r"(b1));
}

// ------------------------------ core GEMM -----------------------------------
// C[64 x 128] = sum_k (A0*W0 + A0*W1 + A1*W0); A[64,K] row-major, W[128,K]
// row-major (k contiguous). K walked in `nchunk` chunks of 32 from klo.
// 256 threads; warp grid 2(M) x 4(N), warp tile 32x32.
// Padded smem rows: 32 bf16 + pad -> 40 elems (80B); conflict-free ldmatrix.
__device__ __forceinline__ void hgemm_64x128(
    const __nv_bfloat16* __restrict__ A0, const __nv_bfloat16* __restrict__ A1, int lda,
    const __nv_bfloat16* __restrict__ W0, const __nv_bfloat16* __restrict__ W1, int ldw,
    float* __restrict__ C, long ldc, int klo, int nchunk)
{
    extern __shared__ __align__(16) char dynsm[];
    uint32_t sbase = smem_u32(dynsm);
    const int t = threadIdx.x;
    const int lane = t & 31, wid = t >> 5;
    const int wm = (wid & 1) * 32, wn = (wid >> 1) * 32;

    float acc[2][4][4];
#pragma unroll
    for (int i = 0; i < 2; i++)
#pragma unroll
        for (int j = 0; j < 4; j++)
#pragma unroll
            for (int q = 0; q < 4; q++) acc[i][j][q] = 0.f;

#define LOAD_STAGE(bufi, kb) do {                                              \
    uint32_t sb_ = sbase + (uint32_t)(bufi) * STAGE_BYTES;                     \
    _Pragma("unroll")                                                          \
    for (int j_ = 0; j_ < 6; j_++) {                                           \
        int q_ = t + j_ * 256;                                                 \
        const __nv_bfloat16* src_;                                             \
        uint32_t dst_;                                                         \
        if (q_ < 512) {                                                        \
            int sp_ = q_ >> 8, rem_ = q_ & 255;                                \
            int row_ = rem_ >> 2, kc_ = rem_ & 3;                              \
            src_ = (sp_ ? A1 : A0) + (long)row_ * lda + (kb) + kc_ * 8;        \
            dst_ = sb_ + (uint32_t)sp_ * 5120u + (uint32_t)row_ * 80u          \
                 + (uint32_t)kc_ * 16u;                                        \
        } else {                                                               \
            int qq_ = q_ - 512;                                                \
            int sp_ = qq_ >> 9, rem_ = qq_ & 511;                              \
            int row_ = rem_ >> 2, kc_ = rem_ & 3;                              \
            src_ = (sp_ ? W1 : W0) + (long)row_ * ldw + (kb) + kc_ * 8;        \
            dst_ = sb_ + 10240u + (uint32_t)sp_ * 10240u                       \
                 + (uint32_t)row_ * 80u + (uint32_t)kc_ * 16u;                 \
        }                                                                      \
        cp16(dst_, src_);                                                      \
    }                                                                          \
    asm volatile("cp.async.commit_group;" ::: "memory");                       \
} while (0)

    LOAD_STAGE(0, klo);
    if (nchunk > 1) LOAD_STAGE(1, klo + 32);

    // ldmatrix lane address components
    const int l8 = lane & 7, sel = lane >> 3;
    const uint32_t a_row = (uint32_t)((sel & 1) * 8 + l8);  // row-in-16
    const uint32_t a_k8  = (uint32_t)((sel >> 1) * 8);      // k8 half
    const uint32_t b_n   = (uint32_t)(((sel >> 1) ? 8 : 0) + l8);  // n-in-16
    const uint32_t b_k8  = (uint32_t)((sel & 1) * 8);

    for (int s = 0; s < nchunk; s++) {
        if (s + 1 < nchunk) asm volatile("cp.async.wait_group 1;" ::: "memory");
        else                asm volatile("cp.async.wait_group 0;" ::: "memory");
        __syncthreads();
        if (s + 2 < nchunk) LOAD_STAGE((s + 2) % NSTAGE, klo + (s + 2) * 32);

        uint32_t sb = sbase + (uint32_t)(s % NSTAGE) * STAGE_BYTES;
        uint32_t A0b = sb, A1b = sb + 5120u, W0b = sb + 10240u, W1b = sb + 20480u;
#pragma unroll
        for (int ko = 0; ko < 32; ko += 16) {
            uint32_t a0r[2][4], a1r[2][4], w0r[2][4], w1r[2][4];
#pragma unroll
            for (int mt = 0; mt < 2; mt++) {
                uint32_t ar = (uint32_t)(wm + mt * 16 + a_row) * 80u + (ko + a_k8) * 2u;
                ldsm4(a0r[mt], A0b + ar);
                ldsm4(a1r[mt], A1b + ar);
            }
#pragma unroll
            for (int np = 0; np < 2; np++) {
                uint32_t br = (uint32_t)(wn + np * 16 + b_n) * 80u + (ko + b_k8) * 2u;
                ldsm4(w0r[np], W0b + br);
                ldsm4(w1r[np], W1b + br);
            }
            // product 0: A0*W0  (8 independent mmas)
#pragma unroll
            for (int mt = 0; mt < 2; mt++)
#pragma unroll
                for (int nt = 0; nt < 4; nt++)
                    mma16816(acc[mt][nt], a0r[mt],
                             w0r[nt >> 1][(nt & 1) * 2], w0r[nt >> 1][(nt & 1) * 2 + 1]);
            // product 1: A0*W1
#pragma unroll
            for (int mt = 0; mt < 2; mt++)
#pragma unroll
                for (int nt = 0; nt < 4; nt++)
                    mma16816(acc[mt][nt], a0r[mt],
                             w1r[nt >> 1][(nt & 1) * 2], w1r[nt >> 1][(nt & 1) * 2 + 1]);
            // product 2: A1*W0
#pragma unroll
            for (int mt = 0; mt < 2; mt++)
#pragma unroll
                for (int nt = 0; nt < 4; nt++)
                    mma16816(acc[mt][nt], a1r[mt],
                             w0r[nt >> 1][(nt & 1) * 2], w0r[nt >> 1][(nt & 1) * 2 + 1]);
        }
        __syncthreads();
    }
#undef LOAD_STAGE

    // epilogue: c frag (mt,nt): rows wm+mt*16+{lane/4, +8}, cols wn+nt*8+(lane%4)*2
    const int row0 = wm + (lane >> 2);
    const int col0 = wn + (lane & 3) * 2;
#pragma unroll
    for (int mt = 0; mt < 2; mt++)
#pragma unroll
        for (int nt = 0; nt < 4; nt++) {
            float* p = C + (long)(row0 + mt * 16) * ldc + col0 + nt * 8;
            *(float2*)p = make_float2(acc[mt][nt][0], acc[mt][nt][1]);
            float* p2 = p + 8 * ldc;
            *(float2*)p2 = make_float2(acc[mt][nt][2], acc[mt][nt][3]);
        }
}

// ------------------------------ kernels -------------------------------------
// One fused split kernel over all fp32->2xbf16 conversions.
#define S0 16384000L
#define S1 17170432L
#define S2 17956864L
#define S3 18743296L
#define S4 19529728L
#define S5 21626880L
#define S6 21889024L
__global__ void __launch_bounds__(256) k_split_all(
    const float* __restrict__ outw, const float* __restrict__ wih0,
    const float* __restrict__ whh0, const float* __restrict__ wih1,
    const float* __restrict__ whh1, const float* __restrict__ ipw,
    const float* __restrict__ hid)
{
    long e0 = (long)blockIdx.x * 1024 + threadIdx.x;
#pragma unroll
    for (int k = 0; k < 4; k++) {
        long e = e0 + k * 256;
        if (e >= S6) return;
        const float* s;
        __nv_bfloat16 *d0, *d1;
        long o;
        if (e < S0)      { s = outw; d0 = g_wo0;  d1 = g_wo1;  o = e; }
        else if (e < S1) { s = wih0; d0 = g_wi00; d1 = g_wi01; o = e - S0; }
        else if (e < S2) { s = whh0; d0 = g_wh00; d1 = g_wh01; o = e - S1; }
        else if (e < S3) { s = wih1; d0 = g_wi10; d1 = g_wi11; o = e - S2; }
        else if (e < S4) { s = whh1; d0 = g_wh10; d1 = g_wh11; o = e - S3; }
        else if (e < S5) { s = ipw;  d0 = g_ip0;  d1 = g_ip1;  o = e - S4; }
        else             { s = hid;  d0 = g_hid0; d1 = g_hid1; o = e - S5; }
        float a = s[o];
        __nv_bfloat16 hi = __float2bfloat16(a);
        d0[o] = hi;
        d1[o] = __float2bfloat16(a - __bfloat162float(hi));
    }
}

__global__ void __launch_bounds__(256) k_inproj(void)
{
    int n0 = blockIdx.x * 128;      // 4 tiles over D=512
    int sp = blockIdx.y;            // 8 K-splits of 512
    hgemm_64x128(g_hid0, g_hid1, H_,
                 g_ip0 + (long)n0 * H_, g_ip1 + (long)n0 * H_, H_,
                 g_ipart + (long)sp * (B_ * D_) + n0, (long)D_, sp * 512, 16);
}

__global__ void __launch_bounds__(256) k_reduce(const float* __restrict__ bias)
{
    int id = blockIdx.x * 256 + threadIdx.x;   // < 32768
    int d = id & (D_ - 1);
    float s = bias[d];
#pragma unroll
    for (int sp = 0; sp < 8; sp++) s += g_ipart[sp * (B_ * D_) + id];
    g_h0f[id] = s;
    g_h1f[id] = s;
    __nv_bfloat16 hi = __float2bfloat16(s);
    __nv_bfloat16 lo = __float2bfloat16(s - __bfloat162float(hi));
    g_h00[id] = hi; g_h01[id] = lo;
    g_h10[id] = hi; g_h11[id] = lo;
    g_x0[id] = __float2bfloat16(0.f);
    g_x1[id] = __float2bfloat16(0.f);
}

__global__ void __launch_bounds__(256) k_gru(int layer)
{
    int j0 = blockIdx.x * 128;      // 24 tiles over virtual 3072 (gi | gh)
    int sp = blockIdx.y;            // 2 K-splits of 256
    const __nv_bfloat16 *A0, *A1, *W0, *W1;
    if (layer == 0) {
        if (j0 < G3) { A0 = g_x0;  A1 = g_x1;  W0 = g_wi00 + (long)j0 * D_;        W1 = g_wi01 + (long)j0 * D_; }
        else         { A0 = g_h00; A1 = g_h01; W0 = g_wh00 + (long)(j0 - G3) * D_; W1 = g_wh01 + (long)(j0 - G3) * D_; }
    } else {
        if (j0 < G3) { A0 = g_h00; A1 = g_h01; W0 = g_wi10 + (long)j0 * D_;        W1 = g_wi11 + (long)j0 * D_; }
        else         { A0 = g_h10; A1 = g_h11; W0 = g_wh10 + (long)(j0 - G3) * D_; W1 = g_wh11 + (long)(j0 - G3) * D_; }
    }
    hgemm_64x128(A0, A1, D_, W0, W1, D_,
                 g_gP + (long)sp * (B_ * 2 * G3) + j0, (long)(2 * G3), sp * 256, 8);
}

__global__ void __launch_bounds__(256) k_combine(
    const float* __restrict__ b_ih, const float* __restrict__ b_hh, int layer)
{
    int id = blockIdx.x * 256 + threadIdx.x;   // < 32768
    int b = id >> 9;
    int d = id & (D_ - 1);
    const float* p0 = g_gP + (long)b * (2 * G3);
    const float* p1 = g_gP + (long)(B_ * 2 * G3) + (long)b * (2 * G3);

    float gir = p0[d]        + p1[d]        + b_ih[d];
    float giz = p0[512 + d]  + p1[512 + d]  + b_ih[512 + d];
    float gin = p0[1024 + d] + p1[1024 + d] + b_ih[1024 + d];
    float ghr = p0[1536 + d] + p1[1536 + d] + b_hh[d];
    float ghz = p0[2048 + d] + p1[2048 + d] + b_hh[512 + d];
    float ghn = p0[2560 + d] + p1[2560 + d] + b_hh[1024 + d];

    float r = 1.f / (1.f + expf(-(gir + ghr)));
    float z = 1.f / (1.f + expf(-(giz + ghz)));
    float n = tanhf(gin + r * ghn);
    float* hf = layer ? g_h1f : g_h0f;
    float hp = hf[id];
    float hn = n + z * (hp - n);
    hf[id] = hn;
    __nv_bfloat16 hi = __float2bfloat16(hn);
    __nv_bfloat16 lo = __float2bfloat16(hn - __bfloat162float(hi));
    if (layer) { g_h10[id] = hi; g_h11[id] = lo; }
    else       { g_h00[id] = hi; g_h01[id] = lo; }
}

__global__ void __launch_bounds__(256) k_logits(float* __restrict__ out, int step)
{
    int n0 = blockIdx.x * 128;      // 250 tiles over V=32000
    hgemm_64x128(g_h10, g_h11, D_,
                 g_wo0 + (long)n0 * D_, g_wo1 + (long)n0 * D_, D_,
                 out + (long)step * V_ + n0, LDOUT, 0, 16);
}

__global__ void __launch_bounds__(256) k_argmax(
    const float* __restrict__ logits, const float* __restrict__ embed)
{
    __shared__ float sv[256];
    __shared__ int   si[256];
    int b = blockIdx.x;
    int t = threadIdx.x;
    const float* row = logits + (long)b * LDOUT;
    float best = -3.4e38f;
    int bi = 0;
    for (int v = t; v < V_; v += 256) {
        float val = row[v];
        if (val > best) { best = val; bi = v; }
    }
    sv[t] = best; si[t] = bi;
    __syncthreads();
    for (int s = 128; s > 0; s >>= 1) {
        if (t < s) {
            if (sv[t + s] > sv[t] || (sv[t + s] == sv[t] && si[t + s] < si[t])) {
                sv[t] = sv[t + s]; si[t] = si[t + s];
            }
        }
        __syncthreads();
    }
    int idx = si[0];
    for (int d = t; d < D_; d += 256) {
        float e = embed[(long)idx * D_ + d];
        __nv_bfloat16 hi = __float2bfloat16(e);
        g_x0[b * D_ + d] = hi;
        g_x1[b * D_ + d] = __float2bfloat16(e - __bfloat162float(hi));
    }
}

// ------------------------------ launch --------------------------------------
extern "C" void kernel_launch(void* const* d_in, const int* in_sizes, int n_in,
                              void* d_out, int out_size)
{
    const float* hid  = (const float*)d_in[0];
    const float* ipw  = (const float*)d_in[1];
    const float* ipb  = (const float*)d_in[2];
    const float* wih0 = (const float*)d_in[3];
    const float* whh0 = (const float*)d_in[4];
    const float* bih0 = (const float*)d_in[5];
    const float* bhh0 = (const float*)d_in[6];
    const float* wih1 = (const float*)d_in[7];
    const float* whh1 = (const float*)d_in[8];
    const float* bih1 = (const float*)d_in[9];
    const float* bhh1 = (const float*)d_in[10];
    const float* emb  = (const float*)d_in[11];
    const float* outw = (const float*)d_in[12];
    float* out = (float*)d_out;

    static int attr_done = 0;
    if (!attr_done) {
        cudaFuncSetAttribute(k_inproj, cudaFuncAttributeMaxDynamicSharedMemorySize, DYN_SMEM);
        cudaFuncSetAttribute(k_gru,    cudaFuncAttributeMaxDynamicSharedMemorySize, DYN_SMEM);
        cudaFuncSetAttribute(k_logits, cudaFuncAttributeMaxDynamicSharedMemorySize, DYN_SMEM);
        attr_done = 1;
    }

    // split all fp32 operands into hi/lo bf16 (one kernel)
    k_split_all<<<(int)((S6 + 1023) / 1024), 256>>>(outw, wih0, whh0, wih1, whh1, ipw, hid);

    // h0 = hidden @ in_proj_w.T + b
    k_inproj<<<dim3(4, 8), 256, DYN_SMEM>>>();
    k_reduce<<<128, 256>>>(ipb);

    for (int t = 0; t < 4; t++) {
        k_gru<<<dim3(24, 2), 256, DYN_SMEM>>>(0);
        k_combine<<<128, 256>>>(bih0, bhh0, 0);
        k_gru<<<dim3(24, 2), 256, DYN_SMEM>>>(1);
        k_combine<<<128, 256>>>(bih1, bhh1, 1);
        k_logits<<<250, 256, DYN_SMEM>>>(out, t);
        if (t < 3) k_argmax<<<64, 256>>>(out + (long)t * V_, emb);
    }
}

// round 5
// speedup vs baseline: 1.9608x; 1.1167x over previous
#include <cuda_runtime.h>
#include <cuda_bf16.h>
#include <math.h>
#include <stdint.h>

// ReDrafter head via mma.sync bf16 (HMMA): B=64, D=512, H=4096, V=32000, K=4.
// Exact 2-way bf16 split of fp32 operands; 3 cross products accumulated fp32.
// R5: GRU split-K=8, inproj split-K=16, argmax fused into logits epilogue.

#define B_ 64
#define D_ 512
#define H_ 4096
#define V_ 32000
#define G3 1536
#define LDOUT 128000L
#define NTILES_V 250

#define STAGE_BYTES 30720        // A0(5120)+A1(5120)+W0(10240)+W1(10240)
#define NSTAGE 3
#define DYN_SMEM (STAGE_BYTES * NSTAGE)

// ------------------------------ device scratch ------------------------------
__device__ __align__(128) __nv_bfloat16 g_wo0[V_ * D_],  g_wo1[V_ * D_];
__device__ __align__(128) __nv_bfloat16 g_wi00[G3 * D_], g_wi01[G3 * D_];
__device__ __align__(128) __nv_bfloat16 g_wh00[G3 * D_], g_wh01[G3 * D_];
__device__ __align__(128) __nv_bfloat16 g_wi10[G3 * D_], g_wi11[G3 * D_];
__device__ __align__(128) __nv_bfloat16 g_wh10[G3 * D_], g_wh11[G3 * D_];
__device__ __align__(128) __nv_bfloat16 g_ip0[D_ * H_],  g_ip1[D_ * H_];
__device__ __align__(128) __nv_bfloat16 g_hid0[B_ * H_], g_hid1[B_ * H_];
__device__ __align__(128) __nv_bfloat16 g_x0[B_ * D_],   g_x1[B_ * D_];
__device__ __align__(128) __nv_bfloat16 g_h00[B_ * D_],  g_h01[B_ * D_];
__device__ __align__(128) __nv_bfloat16 g_h10[B_ * D_],  g_h11[B_ * D_];
__device__ float g_h0f[B_ * D_];
__device__ float g_h1f[B_ * D_];
__device__ float g_ipart[16 * B_ * D_];
__device__ float g_gP[8 * B_ * 2 * G3];
__device__ float g_candV[NTILES_V * B_];
__device__ int   g_candI[NTILES_V * B_];

// ------------------------------ helpers -------------------------------------
__device__ __forceinline__ uint32_t smem_u32(const void* p) {
    uint32_t a;
    asm("{ .reg .u64 t; cvta.to.shared.u64 t, %1; cvt.u32.u64 %0, t; }" : "=r"(a) : "l"(p));
    return a;
}
__device__ __forceinline__ void cp16(uint32_t dst, const void* src) {
    asm volatile("cp.async.cg.shared.global [%0], [%1], 16;" :: "r"(dst), "l"(src));
}
__device__ __forceinline__ void ldsm4(uint32_t* r, uint32_t a) {
    asm volatile("ldmatrix.sync.aligned.m8n8.x4.shared.b16 {%0,%1,%2,%3}, [%4];"
                 : "=r"(r[0]), "=r"(r[1]), "=r"(r[2]), "=r"(r[3]) : "r"(a));
}
__device__ __forceinline__ void mma16816(float* c, const uint32_t* a,
                                         uint32_t b0, uint32_t b1) {
    asm volatile(
        "mma.sync.aligned.m16n8k16.row.col.f32.bf16.bf16.f32 "
        "{%0,%1,%2,%3}, {%4,%5,%6,%7}, {%8,%9}, {%0,%1,%2,%3};"
        : "+f"(c[0]), "+f"(c[1]), "+f"(c[2]), "+f"(c[3])
        : "r"(a[0]), "r"(a[1]), "r"(a[2]), "r"(a[3]), "r"(b0), "r"(b1));
}

// ------------------------------ core GEMM -----------------------------------
// C[64 x 128] = sum_k (A0*W0 + A0*W1 + A1*W0); A[64,K] row-major, W[128,K]
// row-major. K in `nchunk` chunks of 32 from klo. 256 threads; warps 2(M)x4(N),
// warp tile 32x32. Padded smem rows (80B) -> conflict-free ldmatrix.
// If tile >= 0: also emit per-row argmax candidate over this tile's 128 cols.
__device__ __forceinline__ void hgemm_64x128(
    const __nv_bfloat16* __restrict__ A0, const __nv_bfloat16* __restrict__ A1, int lda,
    const __nv_bfloat16* __restrict__ W0, const __nv_bfloat16* __restrict__ W1, int ldw,
    float* __restrict__ C, long ldc, int klo, int nchunk, int tile, int n0)
{
    extern __shared__ __align__(16) char dynsm[];
    __shared__ float sv[4][64];
    __shared__ int   si[4][64];
    uint32_t sbase = smem_u32(dynsm);
    const int t = threadIdx.x;
    const int lane = t & 31, wid = t >> 5;
    const int wm = (wid & 1) * 32, wn = (wid >> 1) * 32;

    float acc[2][4][4];
#pragma unroll
    for (int i = 0; i < 2; i++)
#pragma unroll
        for (int j = 0; j < 4; j++)
#pragma unroll
            for (int q = 0; q < 4; q++) acc[i][j][q] = 0.f;

#define LOAD_STAGE(bufi, kb) do {                                              \
    uint32_t sb_ = sbase + (uint32_t)(bufi) * STAGE_BYTES;                     \
    _Pragma("unroll")                                                          \
    for (int j_ = 0; j_ < 6; j_++) {                                           \
        int q_ = t + j_ * 256;                                                 \
        const __nv_bfloat16* src_;                                             \
        uint32_t dst_;                                                         \
        if (q_ < 512) {                                                        \
            int sp_ = q_ >> 8, rem_ = q_ & 255;                                \
            int row_ = rem_ >> 2, kc_ = rem_ & 3;                              \
            src_ = (sp_ ? A1 : A0) + (long)row_ * lda + (kb) + kc_ * 8;        \
            dst_ = sb_ + (uint32_t)sp_ * 5120u + (uint32_t)row_ * 80u          \
                 + (uint32_t)kc_ * 16u;                                        \
        } else {                                                               \
            int qq_ = q_ - 512;                                                \
            int sp_ = qq_ >> 9, rem_ = qq_ & 511;                              \
            int row_ = rem_ >> 2, kc_ = rem_ & 3;                              \
            src_ = (sp_ ? W1 : W0) + (long)row_ * ldw + (kb) + kc_ * 8;        \
            dst_ = sb_ + 10240u + (uint32_t)sp_ * 10240u                       \
                 + (uint32_t)row_ * 80u + (uint32_t)kc_ * 16u;                 \
        }                                                                      \
        cp16(dst_, src_);                                                      \
    }                                                                          \
    asm volatile("cp.async.commit_group;" ::: "memory");                       \
} while (0)

    LOAD_STAGE(0, klo);
    if (nchunk > 1) LOAD_STAGE(1, klo + 32);

    const int l8 = lane & 7, sel = lane >> 3;
    const uint32_t a_row = (uint32_t)((sel & 1) * 8 + l8);
    const uint32_t a_k8  = (uint32_t)((sel >> 1) * 8);
    const uint32_t b_n   = (uint32_t)(((sel >> 1) ? 8 : 0) + l8);
    const uint32_t b_k8  = (uint32_t)((sel & 1) * 8);

    for (int s = 0; s < nchunk; s++) {
        if (s + 1 < nchunk) asm volatile("cp.async.wait_group 1;" ::: "memory");
        else                asm volatile("cp.async.wait_group 0;" ::: "memory");
        __syncthreads();
        if (s + 2 < nchunk) LOAD_STAGE((s + 2) % NSTAGE, klo + (s + 2) * 32);

        uint32_t sb = sbase + (uint32_t)(s % NSTAGE) * STAGE_BYTES;
        uint32_t A0b = sb, A1b = sb + 5120u, W0b = sb + 10240u, W1b = sb + 20480u;
#pragma unroll
        for (int ko = 0; ko < 32; ko += 16) {
            uint32_t a0r[2][4], a1r[2][4], w0r[2][4], w1r[2][4];
#pragma unroll
            for (int mt = 0; mt < 2; mt++) {
                uint32_t ar = (uint32_t)(wm + mt * 16 + a_row) * 80u + (ko + a_k8) * 2u;
                ldsm4(a0r[mt], A0b + ar);
                ldsm4(a1r[mt], A1b + ar);
            }
#pragma unroll
            for (int np = 0; np < 2; np++) {
                uint32_t br = (uint32_t)(wn + np * 16 + b_n) * 80u + (ko + b_k8) * 2u;
                ldsm4(w0r[np], W0b + br);
                ldsm4(w1r[np], W1b + br);
            }
#pragma unroll
            for (int mt = 0; mt < 2; mt++)
#pragma unroll
                for (int nt = 0; nt < 4; nt++)
                    mma16816(acc[mt][nt], a0r[mt],
                             w0r[nt >> 1][(nt & 1) * 2], w0r[nt >> 1][(nt & 1) * 2 + 1]);
#pragma unroll
            for (int mt = 0; mt < 2; mt++)
#pragma unroll
                for (int nt = 0; nt < 4; nt++)
                    mma16816(acc[mt][nt], a0r[mt],
                             w1r[nt >> 1][(nt & 1) * 2], w1r[nt >> 1][(nt & 1) * 2 + 1]);
#pragma unroll
            for (int mt = 0; mt < 2; mt++)
#pragma unroll
                for (int nt = 0; nt < 4; nt++)
                    mma16816(acc[mt][nt], a1r[mt],
                             w0r[nt >> 1][(nt & 1) * 2], w0r[nt >> 1][(nt & 1) * 2 + 1]);
        }
        __syncthreads();
    }
#undef LOAD_STAGE

    // epilogue: frag (mt,nt): rows wm+mt*16+{lane/4, +8}, cols wn+nt*8+(lane%4)*2
    const int row0 = wm + (lane >> 2);
    const int col0 = wn + (lane & 3) * 2;
#pragma unroll
    for (int mt = 0; mt < 2; mt++)
#pragma unroll
        for (int nt = 0; nt < 4; nt++) {
            float* p = C + (long)(row0 + mt * 16) * ldc + col0 + nt * 8;
            *(float2*)p = make_float2(acc[mt][nt][0], acc[mt][nt][1]);
            float* p2 = p + 8 * ldc;
            *(float2*)p2 = make_float2(acc[mt][nt][2], acc[mt][nt][3]);
        }

    if (tile >= 0) {
        // per-row argmax over this tile's 128 columns, exact lowest-idx tie-break
#pragma unroll
        for (int mt = 0; mt < 2; mt++)
#pragma unroll
            for (int h = 0; h < 2; h++) {
                float bv = -3.4e38f;
                int bi = 0x7FFFFFFF;
#pragma unroll
                for (int nt = 0; nt < 4; nt++) {
                    int c = wn + nt * 8 + (lane & 3) * 2;
                    float v0 = acc[mt][nt][h * 2];
                    float v1 = acc[mt][nt][h * 2 + 1];
                    if (v0 > bv || (v0 == bv && c < bi))      { bv = v0; bi = c; }
                    if (v1 > bv || (v1 == bv && c + 1 < bi))  { bv = v1; bi = c + 1; }
                }
#pragma unroll
                for (int off = 1; off <= 2; off <<= 1) {
                    float ov = __shfl_xor_sync(0xFFFFFFFF, bv, off);
                    int   oi = __shfl_xor_sync(0xFFFFFFFF, bi, off);
                    if (ov > bv || (ov == bv && oi < bi)) { bv = ov; bi = oi; }
                }
                if ((lane & 3) == 0) {
                    int r = wm + mt * 16 + (lane >> 2) + h * 8;
                    sv[wid >> 1][r] = bv;
                    si[wid >> 1][r] = bi;
                }
            }
        __syncthreads();
        if (t < 64) {
            float bv = sv[0][t];
            int bi = si[0][t];
#pragma unroll
            for (int g = 1; g < 4; g++) {
                float v = sv[g][t];
                int i = si[g][t];
                if (v > bv || (v == bv && i < bi)) { bv = v; bi = i; }
            }
            g_candV[tile * B_ + t] = bv;
            g_candI[tile * B_ + t] = n0 + bi;
        }
    }
}

// ------------------------------ kernels -------------------------------------
#define S0 16384000L
#define S1 17170432L
#define S2 17956864L
#define S3 18743296L
#define S4 19529728L
#define S5 21626880L
#define S6 21889024L
__global__ void __launch_bounds__(256) k_split_all(
    const float* __restrict__ outw, const float* __restrict__ wih0,
    const float* __restrict__ whh0, const float* __restrict__ wih1,
    const float* __restrict__ whh1, const float* __restrict__ ipw,
    const float* __restrict__ hid)
{
    long e0 = (long)blockIdx.x * 1024 + threadIdx.x;
#pragma unroll
    for (int k = 0; k < 4; k++) {
        long e = e0 + k * 256;
        if (e >= S6) return;
        const float* s;
        __nv_bfloat16 *d0, *d1;
        long o;
        if (e < S0)      { s = outw; d0 = g_wo0;  d1 = g_wo1;  o = e; }
        else if (e < S1) { s = wih0; d0 = g_wi00; d1 = g_wi01; o = e - S0; }
        else if (e < S2) { s = whh0; d0 = g_wh00; d1 = g_wh01; o = e - S1; }
        else if (e < S3) { s = wih1; d0 = g_wi10; d1 = g_wi11; o = e - S2; }
        else if (e < S4) { s = whh1; d0 = g_wh10; d1 = g_wh11; o = e - S3; }
        else if (e < S5) { s = ipw;  d0 = g_ip0;  d1 = g_ip1;  o = e - S4; }
        else             { s = hid;  d0 = g_hid0; d1 = g_hid1; o = e - S5; }
        float a = s[o];
        __nv_bfloat16 hi = __float2bfloat16(a);
        d0[o] = hi;
        d1[o] = __float2bfloat16(a - __bfloat162float(hi));
    }
}

__global__ void __launch_bounds__(256) k_inproj(void)
{
    int n0 = blockIdx.x * 128;      // 4 tiles over D=512
    int sp = blockIdx.y;            // 16 K-splits of 256
    hgemm_64x128(g_hid0, g_hid1, H_,
                 g_ip0 + (long)n0 * H_, g_ip1 + (long)n0 * H_, H_,
                 g_ipart + (long)sp * (B_ * D_) + n0, (long)D_, sp * 256, 8, -1, 0);
}

__global__ void __launch_bounds__(256) k_reduce(const float* __restrict__ bias)
{
    int id = blockIdx.x * 256 + threadIdx.x;   // < 32768
    int d = id & (D_ - 1);
    float s = bias[d];
#pragma unroll
    for (int sp = 0; sp < 16; sp++) s += g_ipart[sp * (B_ * D_) + id];
    g_h0f[id] = s;
    g_h1f[id] = s;
    __nv_bfloat16 hi = __float2bfloat16(s);
    __nv_bfloat16 lo = __float2bfloat16(s - __bfloat162float(hi));
    g_h00[id] = hi; g_h01[id] = lo;
    g_h10[id] = hi; g_h11[id] = lo;
    g_x0[id] = __float2bfloat16(0.f);
    g_x1[id] = __float2bfloat16(0.f);
}

__global__ void __launch_bounds__(256) k_gru(int layer)
{
    int j0 = blockIdx.x * 128;      // 24 tiles over virtual 3072 (gi | gh)
    int sp = blockIdx.y;            // 8 K-splits of 64
    const __nv_bfloat16 *A0, *A1, *W0, *W1;
    if (layer == 0) {
        if (j0 < G3) { A0 = g_x0;  A1 = g_x1;  W0 = g_wi00 + (long)j0 * D_;        W1 = g_wi01 + (long)j0 * D_; }
        else         { A0 = g_h00; A1 = g_h01; W0 = g_wh00 + (long)(j0 - G3) * D_; W1 = g_wh01 + (long)(j0 - G3) * D_; }
    } else {
        if (j0 < G3) { A0 = g_h00; A1 = g_h01; W0 = g_wi10 + (long)j0 * D_;        W1 = g_wi11 + (long)j0 * D_; }
        else         { A0 = g_h10; A1 = g_h11; W0 = g_wh10 + (long)(j0 - G3) * D_; W1 = g_wh11 + (long)(j0 - G3) * D_; }
    }
    hgemm_64x128(A0, A1, D_, W0, W1, D_,
                 g_gP + (long)sp * (B_ * 2 * G3) + j0, (long)(2 * G3), sp * 64, 2, -1, 0);
}

__global__ void __launch_bounds__(256) k_combine(
    const float* __restrict__ b_ih, const float* __restrict__ b_hh, int layer)
{
    int id = blockIdx.x * 256 + threadIdx.x;   // < 32768
    int b = id >> 9;
    int d = id & (D_ - 1);
    long base = (long)b * (2 * G3);
    float s[6] = {0.f, 0.f, 0.f, 0.f, 0.f, 0.f};
#pragma unroll
    for (int sp = 0; sp < 8; sp++) {
        const float* p = g_gP + (long)sp * (B_ * 2 * G3) + base;
        s[0] += p[d];        s[1] += p[512 + d];  s[2] += p[1024 + d];
        s[3] += p[1536 + d]; s[4] += p[2048 + d]; s[5] += p[2560 + d];
    }
    float gir = s[0] + b_ih[d];
    float giz = s[1] + b_ih[512 + d];
    float gin = s[2] + b_ih[1024 + d];
    float ghr = s[3] + b_hh[d];
    float ghz = s[4] + b_hh[512 + d];
    float ghn = s[5] + b_hh[1024 + d];

    float r = 1.f / (1.f + expf(-(gir + ghr)));
    float z = 1.f / (1.f + expf(-(giz + ghz)));
    float n = tanhf(gin + r * ghn);
    float* hf = layer ? g_h1f : g_h0f;
    float hp = hf[id];
    float hn = n + z * (hp - n);
    hf[id] = hn;
    __nv_bfloat16 hi = __float2bfloat16(hn);
    __nv_bfloat16 lo = __float2bfloat16(hn - __bfloat162float(hi));
    if (layer) { g_h10[id] = hi; g_h11[id] = lo; }
    else       { g_h00[id] = hi; g_h01[id] = lo; }
}

__global__ void __launch_bounds__(256) k_logits(float* __restrict__ out, int step,
                                                int do_cand)
{
    int tile = blockIdx.x;
    int n0 = tile * 128;            // 250 tiles over V=32000
    hgemm_64x128(g_h10, g_h11, D_,
                 g_wo0 + (long)n0 * D_, g_wo1 + (long)n0 * D_, D_,
                 out + (long)step * V_ + n0, LDOUT, 0, 16,
                 do_cand ? tile : -1, n0);
}

// reduce 250 per-tile candidates per row; gather embed row -> x0/x1
__global__ void __launch_bounds__(256) k_select(const float* __restrict__ embed)
{
    __shared__ float sv[256];
    __shared__ int   si[256];
    int b = blockIdx.x;
    int t = threadIdx.x;
    float bv = -3.4e38f;
    int bi = 0x7FFFFFFF;
    if (t < NTILES_V) { bv = g_candV[t * B_ + b]; bi = g_candI[t * B_ + b]; }
    sv[t] = bv; si[t] = bi;
    __syncthreads();
    for (int s = 128; s > 0; s >>= 1) {
        if (t < s) {
            if (sv[t + s] > sv[t] || (sv[t + s] == sv[t] && si[t + s] < si[t])) {
                sv[t] = sv[t + s]; si[t] = si[t + s];
            }
        }
        __syncthreads();
    }
    int idx = si[0];
    for (int d = t; d < D_; d += 256) {
        float e = embed[(long)idx * D_ + d];
        __nv_bfloat16 hi = __float2bfloat16(e);
        g_x0[b * D_ + d] = hi;
        g_x1[b * D_ + d] = __float2bfloat16(e - __bfloat162float(hi));
    }
}

// ------------------------------ launch --------------------------------------
extern "C" void kernel_launch(void* const* d_in, const int* in_sizes, int n_in,
                              void* d_out, int out_size)
{
    const float* hid  = (const float*)d_in[0];
    const float* ipw  = (const float*)d_in[1];
    const float* ipb  = (const float*)d_in[2];
    const float* wih0 = (const float*)d_in[3];
    const float* whh0 = (const float*)d_in[4];
    const float* bih0 = (const float*)d_in[5];
    const float* bhh0 = (const float*)d_in[6];
    const float* wih1 = (const float*)d_in[7];
    const float* whh1 = (const float*)d_in[8];
    const float* bih1 = (const float*)d_in[9];
    const float* bhh1 = (const float*)d_in[10];
    const float* emb  = (const float*)d_in[11];
    const float* outw = (const float*)d_in[12];
    float* out = (float*)d_out;

    static int attr_done = 0;
    if (!attr_done) {
        cudaFuncSetAttribute(k_inproj, cudaFuncAttributeMaxDynamicSharedMemorySize, DYN_SMEM);
        cudaFuncSetAttribute(k_gru,    cudaFuncAttributeMaxDynamicSharedMemorySize, DYN_SMEM);
        cudaFuncSetAttribute(k_logits, cudaFuncAttributeMaxDynamicSharedMemorySize, DYN_SMEM);
        attr_done = 1;
    }

    k_split_all<<<(int)((S6 + 1023) / 1024), 256>>>(outw, wih0, whh0, wih1, whh1, ipw, hid);

    k_inproj<<<dim3(4, 16), 256, DYN_SMEM>>>();
    k_reduce<<<128, 256>>>(ipb);

    for (int t = 0; t < 4; t++) {
        k_gru<<<dim3(24, 8), 256, DYN_SMEM>>>(0);
        k_combine<<<128, 256>>>(bih0, bhh0, 0);
        k_gru<<<dim3(24, 8), 256, DYN_SMEM>>>(1);
        k_combine<<<128, 256>>>(bih1, bhh1, 1);
        k_logits<<<NTILES_V, 256, DYN_SMEM>>>(out, t, t < 3 ? 1 : 0);
        if (t < 3) k_select<<<64, 256>>>(emb);
    }
}

// round 8
// speedup vs baseline: 1.9888x; 1.0143x over previous
#include <cuda_runtime.h>
#include <cuda_bf16.h>
#include <math.h>
#include <stdint.h>

// ReDrafterHead via mma.sync bf16 (HMMA), multi-kernel. B=64, D=512, H=4096,
// V=32000, K=4. Exact 2-way bf16 split, 3 cross products, fp32 accum.
// R8: L2 cache policies — GRU weights evict_last (stay resident), logits /
// inproj weights evict_first (don't thrash L2), logits output streaming stores.

#define B_ 64
#define D_ 512
#define H_ 4096
#define V_ 32000
#define G3 1536
#define LDOUT 128000L
#define NTILES_V 250

#define STAGE_BYTES 30720        // A0(5120)+A1(5120)+W0(10240)+W1(10240)
#define NSTAGE 3
#define DYN_SMEM (STAGE_BYTES * NSTAGE)

// ------------------------------ device scratch ------------------------------
__device__ __align__(128) __nv_bfloat16 g_wo0[V_ * D_],  g_wo1[V_ * D_];
__device__ __align__(128) __nv_bfloat16 g_wi00[G3 * D_], g_wi01[G3 * D_];
__device__ __align__(128) __nv_bfloat16 g_wh00[G3 * D_], g_wh01[G3 * D_];
__device__ __align__(128) __nv_bfloat16 g_wi10[G3 * D_], g_wi11[G3 * D_];
__device__ __align__(128) __nv_bfloat16 g_wh10[G3 * D_], g_wh11[G3 * D_];
__device__ __align__(128) __nv_bfloat16 g_ip0[D_ * H_],  g_ip1[D_ * H_];
__device__ __align__(128) __nv_bfloat16 g_hid0[B_ * H_], g_hid1[B_ * H_];
__device__ __align__(128) __nv_bfloat16 g_x0[B_ * D_],   g_x1[B_ * D_];
__device__ __align__(128) __nv_bfloat16 g_h00[B_ * D_],  g_h01[B_ * D_];
__device__ __align__(128) __nv_bfloat16 g_h10[B_ * D_],  g_h11[B_ * D_];
__device__ float g_h0f[B_ * D_];
__device__ float g_h1f[B_ * D_];
__device__ float g_ipart[16 * B_ * D_];
__device__ float g_gP[8 * B_ * 2 * G3];
__device__ float g_candV[NTILES_V * B_];
__device__ int   g_candI[NTILES_V * B_];

// ------------------------------ helpers -------------------------------------
__device__ __forceinline__ uint32_t smem_u32(const void* p) {
    uint32_t a;
    asm("{ .reg .u64 t; cvta.to.shared.u64 t, %1; cvt.u32.u64 %0, t; }" : "=r"(a) : "l"(p));
    return a;
}
__device__ __forceinline__ void cp16(uint32_t dst, const void* src) {
    asm volatile("cp.async.cg.shared.global [%0], [%1], 16;" :: "r"(dst), "l"(src));
}
__device__ __forceinline__ void cp16pol(uint32_t dst, const void* src, uint64_t pol) {
    asm volatile("cp.async.cg.shared.global.L2::cache_hint [%0], [%1], 16, %2;"
                 :: "r"(dst), "l"(src), "l"(pol));
}
__device__ __forceinline__ uint64_t pol_evict_last() {
    uint64_t p;
    asm("createpolicy.fractional.L2::evict_last.b64 %0, 1.0;" : "=l"(p));
    return p;
}
__device__ __forceinline__ uint64_t pol_evict_first() {
    uint64_t p;
    asm("createpolicy.fractional.L2::evict_first.b64 %0, 1.0;" : "=l"(p));
    return p;
}
__device__ __forceinline__ void ldsm4(uint32_t* r, uint32_t a) {
    asm volatile("ldmatrix.sync.aligned.m8n8.x4.shared.b16 {%0,%1,%2,%3}, [%4];"
                 : "=r"(r[0]), "=r"(r[1]), "=r"(r[2]), "=r"(r[3]) : "r"(a));
}
__device__ __forceinline__ void mma16816(float* c, const uint32_t* a,
                                         uint32_t b0, uint32_t b1) {
    asm volatile(
        "mma.sync.aligned.m16n8k16.row.col.f32.bf16.bf16.f32 "
        "{%0,%1,%2,%3}, {%4,%5,%6,%7}, {%8,%9}, {%0,%1,%2,%3};"
        : "+f"(c[0]), "+f"(c[1]), "+f"(c[2]), "+f"(c[3])
        : "r"(a[0]), "r"(a[1]), "r"(a[2]), "r"(a[3]), "r"(b0), "r"(b1));
}
__device__ __forceinline__ void st2cs(float* p, float x, float y) {
    asm volatile("st.global.cs.v2.f32 [%0], {%1, %2};" :: "l"(p), "f"(x), "f"(y)
                 : "memory");
}

// ------------------------------ core GEMM -----------------------------------
// C[64 x 128] = sum_k (A0*W0 + A0*W1 + A1*W0); A[64,K], W[128,K] row-major.
// K in `nchunk` chunks of 32 from klo. 256 threads; warps 2(M)x4(N), 32x32.
// 80B-padded smem rows -> conflict-free ldmatrix. W loads carry L2 policy
// `wpol`. If streamc: C stored with .cs. If tile>=0: emit argmax candidates.
__device__ __forceinline__ void hgemm_64x128(
    const __nv_bfloat16* __restrict__ A0, const __nv_bfloat16* __restrict__ A1, int lda,
    const __nv_bfloat16* __restrict__ W0, const __nv_bfloat16* __restrict__ W1, int ldw,
    float* __restrict__ C, long ldc, int klo, int nchunk,
    uint64_t wpol, bool streamc, int tile, int n0)
{
    extern __shared__ __align__(16) char dynsm[];
    __shared__ float sv[4][64];
    __shared__ int   si[4][64];
    uint32_t sbase = smem_u32(dynsm);
    const int t = threadIdx.x;
    const int lane = t & 31, wid = t >> 5;
    const int wm = (wid & 1) * 32, wn = (wid >> 1) * 32;

    float acc[2][4][4];
#pragma unroll
    for (int i = 0; i < 2; i++)
#pragma unroll
        for (int j = 0; j < 4; j++)
#pragma unroll
            for (int q = 0; q < 4; q++) acc[i][j][q] = 0.f;

#define LOAD_STAGE(bufi, kb) do {                                              \
    uint32_t sb_ = sbase + (uint32_t)(bufi) * STAGE_BYTES;                     \
    _Pragma("unroll")                                                          \
    for (int j_ = 0; j_ < 6; j_++) {                                           \
        int q_ = t + j_ * 256;                                                 \
        if (q_ < 512) {                                                        \
            int sp_ = q_ >> 8, rem_ = q_ & 255;                                \
            int row_ = rem_ >> 2, kc_ = rem_ & 3;                              \
            cp16(sb_ + (uint32_t)sp_ * 5120u + (uint32_t)row_ * 80u            \
                     + (uint32_t)kc_ * 16u,                                    \
                 (sp_ ? A1 : A0) + (long)row_ * lda + (kb) + kc_ * 8);         \
        } else {                                                               \
            int qq_ = q_ - 512;                                                \
            int sp_ = qq_ >> 9, rem_ = qq_ & 511;                              \
            int row_ = rem_ >> 2, kc_ = rem_ & 3;                              \
            cp16pol(sb_ + 10240u + (uint32_t)sp_ * 10240u                      \
                        + (uint32_t)row_ * 80u + (uint32_t)kc_ * 16u,          \
                    (sp_ ? W1 : W0) + (long)row_ * ldw + (kb) + kc_ * 8,       \
                    wpol);                                                     \
        }                                                                      \
    }                                                                          \
    asm volatile("cp.async.commit_group;" ::: "memory");                       \
} while (0)

    LOAD_STAGE(0, klo);
    if (nchunk > 1) LOAD_STAGE(1, klo + 32);

    const int l8 = lane & 7, sel = lane >> 3;
    const uint32_t a_row = (uint32_t)((sel & 1) * 8 + l8);
    const uint32_t a_k8  = (uint32_t)((sel >> 1) * 8);
    const uint32_t b_n   = (uint32_t)(((sel >> 1) ? 8 : 0) + l8);
    const uint32_t b_k8  = (uint32_t)((sel & 1) * 8);

    for (int s = 0; s < nchunk; s++) {
        if (s + 1 < nchunk) asm volatile("cp.async.wait_group 1;" ::: "memory");
        else                asm volatile("cp.async.wait_group 0;" ::: "memory");
        __syncthreads();
        if (s + 2 < nchunk) LOAD_STAGE((s + 2) % NSTAGE, klo + (s + 2) * 32);

        uint32_t sb = sbase + (uint32_t)(s % NSTAGE) * STAGE_BYTES;
        uint32_t A0b = sb, A1b = sb + 5120u, W0b = sb + 10240u, W1b = sb + 20480u;
#pragma unroll
        for (int ko = 0; ko < 32; ko += 16) {
            uint32_t a0r[2][4], a1r[2][4], w0r[2][4], w1r[2][4];
#pragma unroll
            for (int mt = 0; mt < 2; mt++) {
                uint32_t ar = (uint32_t)(wm + mt * 16 + a_row) * 80u + (ko + a_k8) * 2u;
                ldsm4(a0r[mt], A0b + ar);
                ldsm4(a1r[mt], A1b + ar);
            }
#pragma unroll
            for (int np = 0; np < 2; np++) {
                uint32_t br = (uint32_t)(wn + np * 16 + b_n) * 80u + (ko + b_k8) * 2u;
                ldsm4(w0r[np], W0b + br);
                ldsm4(w1r[np], W1b + br);
            }
#pragma unroll
            for (int mt = 0; mt < 2; mt++)
#pragma unroll
                for (int nt = 0; nt < 4; nt++)
                    mma16816(acc[mt][nt], a0r[mt],
                             w0r[nt >> 1][(nt & 1) * 2], w0r[nt >> 1][(nt & 1) * 2 + 1]);
#pragma unroll
            for (int mt = 0; mt < 2; mt++)
#pragma unroll
                for (int nt = 0; nt < 4; nt++)
                    mma16816(acc[mt][nt], a0r[mt],
                             w1r[nt >> 1][(nt & 1) * 2], w1r[nt >> 1][(nt & 1) * 2 + 1]);
#pragma unroll
            for (int mt = 0; mt < 2; mt++)
#pragma unroll
                for (int nt = 0; nt < 4; nt++)
                    mma16816(acc[mt][nt], a1r[mt],
                             w0r[nt >> 1][(nt & 1) * 2], w0r[nt >> 1][(nt & 1) * 2 + 1]);
        }
        __syncthreads();
    }
#undef LOAD_STAGE

    const int row0 = wm + (lane >> 2);
    const int col0 = wn + (lane & 3) * 2;
#pragma unroll
    for (int mt = 0; mt < 2; mt++)
#pragma unroll
        for (int nt = 0; nt < 4; nt++) {
            float* p = C + (long)(row0 + mt * 16) * ldc + col0 + nt * 8;
            float* p2 = p + 8 * ldc;
            if (streamc) {
                st2cs(p,  acc[mt][nt][0], acc[mt][nt][1]);
                st2cs(p2, acc[mt][nt][2], acc[mt][nt][3]);
            } else {
                *(float2*)p  = make_float2(acc[mt][nt][0], acc[mt][nt][1]);
                *(float2*)p2 = make_float2(acc[mt][nt][2], acc[mt][nt][3]);
            }
        }

    if (tile >= 0) {
#pragma unroll
        for (int mt = 0; mt < 2; mt++)
#pragma unroll
            for (int h = 0; h < 2; h++) {
                float bv = -3.4e38f;
                int bi = 0x7FFFFFFF;
#pragma unroll
                for (int nt = 0; nt < 4; nt++) {
                    int cc = wn + nt * 8 + (lane & 3) * 2;
                    float v0 = acc[mt][nt][h * 2];
                    float v1 = acc[mt][nt][h * 2 + 1];
                    if (v0 > bv || (v0 == bv && cc < bi))     { bv = v0; bi = cc; }
                    if (v1 > bv || (v1 == bv && cc + 1 < bi)) { bv = v1; bi = cc + 1; }
                }
#pragma unroll
                for (int off = 1; off <= 2; off <<= 1) {
                    float ov = __shfl_xor_sync(0xFFFFFFFF, bv, off);
                    int   oi = __shfl_xor_sync(0xFFFFFFFF, bi, off);
                    if (ov > bv || (ov == bv && oi < bi)) { bv = ov; bi = oi; }
                }
                if ((lane & 3) == 0) {
                    int r = wm + mt * 16 + (lane >> 2) + h * 8;
                    sv[wid >> 1][r] = bv;
                    si[wid >> 1][r] = bi;
                }
            }
        __syncthreads();
        if (t < 64) {
            float bv = sv[0][t];
            int bi = si[0][t];
#pragma unroll
            for (int g = 1; g < 4; g++) {
                float v = sv[g][t];
                int i = si[g][t];
                if (v > bv || (v == bv && i < bi)) { bv = v; bi = i; }
            }
            g_candV[tile * B_ + t] = bv;
            g_candI[tile * B_ + t] = n0 + bi;
        }
    }
}

// ------------------------------ kernels -------------------------------------
#define S0 16384000L
#define S1 17170432L
#define S2 17956864L
#define S3 18743296L
#define S4 19529728L
#define S5 21626880L
#define S6 21889024L
__global__ void __launch_bounds__(256) k_split_all(
    const float* __restrict__ outw, const float* __restrict__ wih0,
    const float* __restrict__ whh0, const float* __restrict__ wih1,
    const float* __restrict__ whh1, const float* __restrict__ ipw,
    const float* __restrict__ hid)
{
    long e0 = (long)blockIdx.x * 1024 + threadIdx.x;
#pragma unroll
    for (int k = 0; k < 4; k++) {
        long e = e0 + k * 256;
        if (e >= S6) return;
        const float* s;
        __nv_bfloat16 *d0, *d1;
        long o;
        if (e < S0)      { s = outw; d0 = g_wo0;  d1 = g_wo1;  o = e; }
        else if (e < S1) { s = wih0; d0 = g_wi00; d1 = g_wi01; o = e - S0; }
        else if (e < S2) { s = whh0; d0 = g_wh00; d1 = g_wh01; o = e - S1; }
        else if (e < S3) { s = wih1; d0 = g_wi10; d1 = g_wi11; o = e - S2; }
        else if (e < S4) { s = whh1; d0 = g_wh10; d1 = g_wh11; o = e - S3; }
        else if (e < S5) { s = ipw;  d0 = g_ip0;  d1 = g_ip1;  o = e - S4; }
        else             { s = hid;  d0 = g_hid0; d1 = g_hid1; o = e - S5; }
        float a = s[o];
        __nv_bfloat16 hi = __float2bfloat16(a);
        d0[o] = hi;
        d1[o] = __float2bfloat16(a - __bfloat162float(hi));
    }
}

__global__ void __launch_bounds__(256) k_inproj(void)
{
    int n0 = blockIdx.x * 128;      // 4 tiles over D=512
    int sp = blockIdx.y;            // 16 K-splits of 256
    hgemm_64x128(g_hid0, g_hid1, H_,
                 g_ip0 + (long)n0 * H_, g_ip1 + (long)n0 * H_, H_,
                 g_ipart + (long)sp * (B_ * D_) + n0, (long)D_, sp * 256, 8,
                 pol_evict_first(), false, -1, 0);
}

__global__ void __launch_bounds__(256) k_reduce(const float* __restrict__ bias)
{
    int id = blockIdx.x * 256 + threadIdx.x;   // < 32768
    int d = id & (D_ - 1);
    float s = bias[d];
#pragma unroll
    for (int sp = 0; sp < 16; sp++) s += g_ipart[sp * (B_ * D_) + id];
    g_h0f[id] = s;
    g_h1f[id] = s;
    __nv_bfloat16 hi = __float2bfloat16(s);
    __nv_bfloat16 lo = __float2bfloat16(s - __bfloat162float(hi));
    g_h00[id] = hi; g_h01[id] = lo;
    g_h10[id] = hi; g_h11[id] = lo;
    g_x0[id] = __float2bfloat16(0.f);
    g_x1[id] = __float2bfloat16(0.f);
}

__global__ void __launch_bounds__(256) k_gru(int layer)
{
    int j0 = blockIdx.x * 128;      // 24 tiles over virtual 3072 (gi | gh)
    int sp = blockIdx.y;            // 8 K-splits of 64
    const __nv_bfloat16 *A0, *A1, *W0, *W1;
    if (layer == 0) {
        if (j0 < G3) { A0 = g_x0;  A1 = g_x1;  W0 = g_wi00 + (long)j0 * D_;        W1 = g_wi01 + (long)j0 * D_; }
        else         { A0 = g_h00; A1 = g_h01; W0 = g_wh00 + (long)(j0 - G3) * D_; W1 = g_wh01 + (long)(j0 - G3) * D_; }
    } else {
        if (j0 < G3) { A0 = g_h00; A1 = g_h01; W0 = g_wi10 + (long)j0 * D_;        W1 = g_wi11 + (long)j0 * D_; }
        else         { A0 = g_h10; A1 = g_h11; W0 = g_wh10 + (long)(j0 - G3) * D_; W1 = g_wh11 + (long)(j0 - G3) * D_; }
    }
    hgemm_64x128(A0, A1, D_, W0, W1, D_,
                 g_gP + (long)sp * (B_ * 2 * G3) + j0, (long)(2 * G3), sp * 64, 2,
                 pol_evict_last(), false, -1, 0);
}

__global__ void __launch_bounds__(256) k_combine(
    const float* __restrict__ b_ih, const float* __restrict__ b_hh, int layer)
{
    int id = blockIdx.x * 256 + threadIdx.x;   // < 32768
    int d = id & (D_ - 1);
    long base = (long)(id >> 9) * (2 * G3);
    float s0 = 0.f, s1 = 0.f, s2 = 0.f, s3 = 0.f, s4 = 0.f, s5 = 0.f;
#pragma unroll
    for (int sp = 0; sp < 8; sp++) {
        const float* p = g_gP + (long)sp * (B_ * 2 * G3) + base;
        s0 += p[d];        s1 += p[512 + d];  s2 += p[1024 + d];
        s3 += p[1536 + d]; s4 += p[2048 + d]; s5 += p[2560 + d];
    }
    float r = 1.f / (1.f + expf(-(s0 + b_ih[d] + s3 + b_hh[d])));
    float z = 1.f / (1.f + expf(-(s1 + b_ih[512 + d] + s4 + b_hh[512 + d])));
    float n = tanhf(s2 + b_ih[1024 + d] + r * (s5 + b_hh[1024 + d]));
    float* hf = layer ? g_h1f : g_h0f;
    float hp = hf[id];
    float hn = n + z * (hp - n);
    hf[id] = hn;
    __nv_bfloat16 hi = __float2bfloat16(hn);
    __nv_bfloat16 lo = __float2bfloat16(hn - __bfloat162float(hi));
    if (layer) { g_h10[id] = hi; g_h11[id] = lo; }
    else       { g_h00[id] = hi; g_h01[id] = lo; }
}

__global__ void __launch_bounds__(256) k_logits(float* __restrict__ out, int step,
                                                int do_cand)
{
    int tile = blockIdx.x;
    int n0 = tile * 128;            // 250 tiles over V=32000
    hgemm_64x128(g_h10, g_h11, D_,
                 g_wo0 + (long)n0 * D_, g_wo1 + (long)n0 * D_, D_,
                 out + (long)step * V_ + n0, LDOUT, 0, 16,
                 pol_evict_first(), true, do_cand ? tile : -1, n0);
}

__global__ void __launch_bounds__(256) k_select(const float* __restrict__ embed)
{
    __shared__ float sv[256];
    __shared__ int   si[256];
    int b = blockIdx.x;
    int t = threadIdx.x;
    float bv = -3.4e38f;
    int bi = 0x7FFFFFFF;
    if (t < NTILES_V) { bv = g_candV[t * B_ + b]; bi = g_candI[t * B_ + b]; }
    sv[t] = bv; si[t] = bi;
    __syncthreads();
    for (int s = 128; s > 0; s >>= 1) {
        if (t < s) {
            if (sv[t + s] > sv[t] || (sv[t + s] == sv[t] && si[t + s] < si[t])) {
                sv[t] = sv[t + s]; si[t] = si[t + s];
            }
        }
        __syncthreads();
    }
    int idx = si[0];
    for (int d = t; d < D_; d += 256) {
        float e = embed[(long)idx * D_ + d];
        __nv_bfloat16 hi = __float2bfloat16(e);
        g_x0[b * D_ + d] = hi;
        g_x1[b * D_ + d] = __float2bfloat16(e - __bfloat162float(hi));
    }
}

// ------------------------------ launch --------------------------------------
extern "C" void kernel_launch(void* const* d_in, const int* in_sizes, int n_in,
                              void* d_out, int out_size)
{
    const float* hid  = (const float*)d_in[0];
    const float* ipw  = (const float*)d_in[1];
    const float* ipb  = (const float*)d_in[2];
    const float* wih0 = (const float*)d_in[3];
    const float* whh0 = (const float*)d_in[4];
    const float* bih0 = (const float*)d_in[5];
    const float* bhh0 = (const float*)d_in[6];
    const float* wih1 = (const float*)d_in[7];
    const float* whh1 = (const float*)d_in[8];
    const float* bih1 = (const float*)d_in[9];
    const float* bhh1 = (const float*)d_in[10];
    const float* emb  = (const float*)d_in[11];
    const float* outw = (const float*)d_in[12];
    float* out = (float*)d_out;

    (void)cudaFuncSetAttribute(k_inproj, cudaFuncAttributeMaxDynamicSharedMemorySize, DYN_SMEM);
    (void)cudaFuncSetAttribute(k_gru,    cudaFuncAttributeMaxDynamicSharedMemorySize, DYN_SMEM);
    (void)cudaFuncSetAttribute(k_logits, cudaFuncAttributeMaxDynamicSharedMemorySize, DYN_SMEM);

    k_split_all<<<(int)((S6 + 1023) / 1024), 256>>>(outw, wih0, whh0, wih1, whh1, ipw, hid);

    k_inproj<<<dim3(4, 16), 256, DYN_SMEM>>>();
    k_reduce<<<128, 256>>>(ipb);

    for (int t = 0; t < 4; t++) {
        k_gru<<<dim3(24, 8), 256, DYN_SMEM>>>(0);
        k_combine<<<128, 256>>>(bih0, bhh0, 0);
        k_gru<<<dim3(24, 8), 256, DYN_SMEM>>>(1);
        k_combine<<<128, 256>>>(bih1, bhh1, 1);
        k_logits<<<NTILES_V, 256, DYN_SMEM>>>(out, t, t < 3 ? 1 : 0);
        if (t < 3) k_select<<<64, 256>>>(emb);
    }
}

// round 9
// speedup vs baseline: 2.0998x; 1.0558x over previous
#include <cuda_runtime.h>
#include <cuda_bf16.h>
#include <math.h>
#include <stdint.h>

// ReDrafterHead via mma.sync bf16 (HMMA), multi-kernel + PDL overlap.
// B=64, D=512, H=4096, V=32000, K=4. Exact 2-way bf16 split, 3 cross
// products, fp32 accum. R9: programmatic dependent launch on the whole chain;
// weight prologues issued before griddepcontrol.wait.

#define B_ 64
#define D_ 512
#define H_ 4096
#define V_ 32000
#define G3 1536
#define LDOUT 128000L
#define NTILES_V 250

#define STAGE_BYTES 30720        // A0(5120)+A1(5120)+W0(10240)+W1(10240)
#define NSTAGE 3
#define DYN_SMEM (STAGE_BYTES * NSTAGE)

#define GD_TRIGGER() asm volatile("griddepcontrol.launch_dependents;" ::: "memory")
#define GD_WAIT()    asm volatile("griddepcontrol.wait;" ::: "memory")

// ------------------------------ device scratch ------------------------------
__device__ __align__(128) __nv_bfloat16 g_wo0[V_ * D_],  g_wo1[V_ * D_];
__device__ __align__(128) __nv_bfloat16 g_wi00[G3 * D_], g_wi01[G3 * D_];
__device__ __align__(128) __nv_bfloat16 g_wh00[G3 * D_], g_wh01[G3 * D_];
__device__ __align__(128) __nv_bfloat16 g_wi10[G3 * D_], g_wi11[G3 * D_];
__device__ __align__(128) __nv_bfloat16 g_wh10[G3 * D_], g_wh11[G3 * D_];
__device__ __align__(128) __nv_bfloat16 g_ip0[D_ * H_],  g_ip1[D_ * H_];
__device__ __align__(128) __nv_bfloat16 g_hid0[B_ * H_], g_hid1[B_ * H_];
__device__ __align__(128) __nv_bfloat16 g_x0[B_ * D_],   g_x1[B_ * D_];
__device__ __align__(128) __nv_bfloat16 g_h00[B_ * D_],  g_h01[B_ * D_];
__device__ __align__(128) __nv_bfloat16 g_h10[B_ * D_],  g_h11[B_ * D_];
__device__ float g_h0f[B_ * D_];
__device__ float g_h1f[B_ * D_];
__device__ float g_ipart[16 * B_ * D_];
__device__ float g_gP[8 * B_ * 2 * G3];
__device__ float g_candV[NTILES_V * B_];
__device__ int   g_candI[NTILES_V * B_];

// ------------------------------ helpers -------------------------------------
__device__ __forceinline__ uint32_t smem_u32(const void* p) {
    uint32_t a;
    asm("{ .reg .u64 t; cvta.to.shared.u64 t, %1; cvt.u32.u64 %0, t; }" : "=r"(a) : "l"(p));
    return a;
}
__device__ __forceinline__ void cp16(uint32_t dst, const void* src) {
    asm volatile("cp.async.cg.shared.global [%0], [%1], 16;" :: "r"(dst), "l"(src));
}
__device__ __forceinline__ void ldsm4(uint32_t* r, uint32_t a) {
    asm volatile("ldmatrix.sync.aligned.m8n8.x4.shared.b16 {%0,%1,%2,%3}, [%4];"
                 : "=r"(r[0]), "=r"(r[1]), "=r"(r[2]), "=r"(r[3]) : "r"(a));
}
__device__ __forceinline__ void mma16816(float* c, const uint32_t* a,
                                         uint32_t b0, uint32_t b1) {
    asm volatile(
        "mma.sync.aligned.m16n8k16.row.col.f32.bf16.bf16.f32 "
        "{%0,%1,%2,%3}, {%4,%5,%6,%7}, {%8,%9}, {%0,%1,%2,%3};"
        : "+f"(c[0]), "+f"(c[1]), "+f"(c[2]), "+f"(c[3])
        : "r"(a[0]), "r"(a[1]), "r"(a[2]), "r"(a[3]), "r"(b0), "r"(b1));
}
__device__ __forceinline__ void st2cs(float* p, float x, float y) {
    asm volatile("st.global.cs.v2.f32 [%0], {%1, %2};" :: "l"(p), "f"(x), "f"(y)
                 : "memory");
}

// ------------------------------ core GEMM -----------------------------------
// C[64 x 128] = sum_k (A0*W0 + A0*W1 + A1*W0); A[64,K], W[128,K] row-major.
// K in `nchunk` chunks of 32 from klo. 256 threads; warps 2(M)x4(N), 32x32.
// 80B-padded smem rows -> conflict-free ldmatrix.
// pdl: 0 = no dependency handling; 1 = W loads of stages 0/1 issued BEFORE
// griddepcontrol.wait (W independent of predecessor), A after; 2 = wait first.
// streamc: C stored with .cs. tile>=0: emit per-row argmax candidates.
__device__ __forceinline__ void hgemm_64x128(
    const __nv_bfloat16* __restrict__ A0, const __nv_bfloat16* __restrict__ A1, int lda,
    const __nv_bfloat16* __restrict__ W0, const __nv_bfloat16* __restrict__ W1, int ldw,
    float* __restrict__ C, long ldc, int klo, int nchunk,
    int pdl, bool streamc, int tile, int n0)
{
    extern __shared__ __align__(16) char dynsm[];
    __shared__ float sv[4][64];
    __shared__ int   si[4][64];
    uint32_t sbase = smem_u32(dynsm);
    const int t = threadIdx.x;
    const int lane = t & 31, wid = t >> 5;
    const int wm = (wid & 1) * 32, wn = (wid >> 1) * 32;

    float acc[2][4][4];
#pragma unroll
    for (int i = 0; i < 2; i++)
#pragma unroll
        for (int j = 0; j < 4; j++)
#pragma unroll
            for (int q = 0; q < 4; q++) acc[i][j][q] = 0.f;

#define LOAD_A(bufi, kb) do {                                                  \
    uint32_t sb_ = sbase + (uint32_t)(bufi) * STAGE_BYTES;                     \
    _Pragma("unroll")                                                          \
    for (int j_ = 0; j_ < 2; j_++) {                                           \
        int q_ = t + j_ * 256;                                                 \
        int sp_ = q_ >> 8, rem_ = q_ & 255;                                    \
        int row_ = rem_ >> 2, kc_ = rem_ & 3;                                  \
        cp16(sb_ + (uint32_t)sp_ * 5120u + (uint32_t)row_ * 80u                \
                 + (uint32_t)kc_ * 16u,                                        \
             (sp_ ? A1 : A0) + (long)row_ * lda + (kb) + kc_ * 8);             \
    }                                                                          \
} while (0)

#define LOAD_W(bufi, kb) do {                                                  \
    uint32_t sb_ = sbase + (uint32_t)(bufi) * STAGE_BYTES;                     \
    _Pragma("unroll")                                                          \
    for (int j_ = 0; j_ < 4; j_++) {                                           \
        int qq_ = t + j_ * 256;                                                \
        int sp_ = qq_ >> 9, rem_ = qq_ & 511;                                  \
        int row_ = rem_ >> 2, kc_ = rem_ & 3;                                  \
        cp16(sb_ + 10240u + (uint32_t)sp_ * 10240u                             \
                 + (uint32_t)row_ * 80u + (uint32_t)kc_ * 16u,                 \
             (sp_ ? W1 : W0) + (long)row_ * ldw + (kb) + kc_ * 8);             \
    }                                                                          \
} while (0)

#define COMMIT() asm volatile("cp.async.commit_group;" ::: "memory")

    if (pdl == 1) {
        // W is independent of the predecessor kernel: prefetch stages 0/1 now.
        LOAD_W(0, klo);
        if (nchunk > 1) LOAD_W(1, klo + 32);
        GD_WAIT();
        LOAD_A(0, klo);
        COMMIT();                       // group0 = {W0, W1, A0}
        if (nchunk > 1) { LOAD_A(1, klo + 32); COMMIT(); }   // group1 = {A1}
    } else {
        if (pdl == 2) GD_WAIT();
        LOAD_A(0, klo); LOAD_W(0, klo); COMMIT();
        if (nchunk > 1) { LOAD_A(1, klo + 32); LOAD_W(1, klo + 32); COMMIT(); }
    }

    const int l8 = lane & 7, sel = lane >> 3;
    const uint32_t a_row = (uint32_t)((sel & 1) * 8 + l8);
    const uint32_t a_k8  = (uint32_t)((sel >> 1) * 8);
    const uint32_t b_n   = (uint32_t)(((sel >> 1) ? 8 : 0) + l8);
    const uint32_t b_k8  = (uint32_t)((sel & 1) * 8);

    for (int s = 0; s < nchunk; s++) {
        if (s + 1 < nchunk) asm volatile("cp.async.wait_group 1;" ::: "memory");
        else                asm volatile("cp.async.wait_group 0;" ::: "memory");
        __syncthreads();
        if (s + 2 < nchunk) {
            int kb2 = klo + (s + 2) * 32;
            LOAD_A((s + 2) % NSTAGE, kb2);
            LOAD_W((s + 2) % NSTAGE, kb2);
            COMMIT();
        }

        uint32_t sb = sbase + (uint32_t)(s % NSTAGE) * STAGE_BYTES;
        uint32_t A0b = sb, A1b = sb + 5120u, W0b = sb + 10240u, W1b = sb + 20480u;
#pragma unroll
        for (int ko = 0; ko < 32; ko += 16) {
            uint32_t a0r[2][4], a1r[2][4], w0r[2][4], w1r[2][4];
#pragma unroll
            for (int mt = 0; mt < 2; mt++) {
                uint32_t ar = (uint32_t)(wm + mt * 16 + a_row) * 80u + (ko + a_k8) * 2u;
                ldsm4(a0r[mt], A0b + ar);
                ldsm4(a1r[mt], A1b + ar);
            }
#pragma unroll
            for (int np = 0; np < 2; np++) {
                uint32_t br = (uint32_t)(wn + np * 16 + b_n) * 80u + (ko + b_k8) * 2u;
                ldsm4(w0r[np], W0b + br);
                ldsm4(w1r[np], W1b + br);
            }
#pragma unroll
            for (int mt = 0; mt < 2; mt++)
#pragma unroll
                for (int nt = 0; nt < 4; nt++)
                    mma16816(acc[mt][nt], a0r[mt],
                             w0r[nt >> 1][(nt & 1) * 2], w0r[nt >> 1][(nt & 1) * 2 + 1]);
#pragma unroll
            for (int mt = 0; mt < 2; mt++)
#pragma unroll
                for (int nt = 0; nt < 4; nt++)
                    mma16816(acc[mt][nt], a0r[mt],
                             w1r[nt >> 1][(nt & 1) * 2], w1r[nt >> 1][(nt & 1) * 2 + 1]);
#pragma unroll
            for (int mt = 0; mt < 2; mt++)
#pragma unroll
                for (int nt = 0; nt < 4; nt++)
                    mma16816(acc[mt][nt], a1r[mt],
                             w0r[nt >> 1][(nt & 1) * 2], w0r[nt >> 1][(nt & 1) * 2 + 1]);
        }
        __syncthreads();
    }
#undef LOAD_A
#undef LOAD_W
#undef COMMIT

    const int row0 = wm + (lane >> 2);
    const int col0 = wn + (lane & 3) * 2;
#pragma unroll
    for (int mt = 0; mt < 2; mt++)
#pragma unroll
        for (int nt = 0; nt < 4; nt++) {
            float* p = C + (long)(row0 + mt * 16) * ldc + col0 + nt * 8;
            float* p2 = p + 8 * ldc;
            if (streamc) {
                st2cs(p,  acc[mt][nt][0], acc[mt][nt][1]);
                st2cs(p2, acc[mt][nt][2], acc[mt][nt][3]);
            } else {
                *(float2*)p  = make_float2(acc[mt][nt][0], acc[mt][nt][1]);
                *(float2*)p2 = make_float2(acc[mt][nt][2], acc[mt][nt][3]);
            }
        }

    if (tile >= 0) {
#pragma unroll
        for (int mt = 0; mt < 2; mt++)
#pragma unroll
            for (int h = 0; h < 2; h++) {
                float bv = -3.4e38f;
                int bi = 0x7FFFFFFF;
#pragma unroll
                for (int nt = 0; nt < 4; nt++) {
                    int cc = wn + nt * 8 + (lane & 3) * 2;
                    float v0 = acc[mt][nt][h * 2];
                    float v1 = acc[mt][nt][h * 2 + 1];
                    if (v0 > bv || (v0 == bv && cc < bi))     { bv = v0; bi = cc; }
                    if (v1 > bv || (v1 == bv && cc + 1 < bi)) { bv = v1; bi = cc + 1; }
                }
#pragma unroll
                for (int off = 1; off <= 2; off <<= 1) {
                    float ov = __shfl_xor_sync(0xFFFFFFFF, bv, off);
                    int   oi = __shfl_xor_sync(0xFFFFFFFF, bi, off);
                    if (ov > bv || (ov == bv && oi < bi)) { bv = ov; bi = oi; }
                }
                if ((lane & 3) == 0) {
                    int r = wm + mt * 16 + (lane >> 2) + h * 8;
                    sv[wid >> 1][r] = bv;
                    si[wid >> 1][r] = bi;
                }
            }
        __syncthreads();
        if (t < 64) {
            float bv = sv[0][t];
            int bi = si[0][t];
#pragma unroll
            for (int g = 1; g < 4; g++) {
                float v = sv[g][t];
                int i = si[g][t];
                if (v > bv || (v == bv && i < bi)) { bv = v; bi = i; }
            }
            g_candV[tile * B_ + t] = bv;
            g_candI[tile * B_ + t] = n0 + bi;
        }
    }
}

// ------------------------------ kernels -------------------------------------
#define S0 16384000L
#define S1 17170432L
#define S2 17956864L
#define S3 18743296L
#define S4 19529728L
#define S5 21626880L
#define S6 21889024L
// NOTE: k_split_all intentionally has NO early trigger — its completion gates
// the whole chain, so later prologue prefetches of split-produced weights are
// always safe.
__global__ void __launch_bounds__(256) k_split_all(
    const float* __restrict__ outw, const float* __restrict__ wih0,
    const float* __restrict__ whh0, const float* __restrict__ wih1,
    const float* __restrict__ whh1, const float* __restrict__ ipw,
    const float* __restrict__ hid)
{
    long e0 = (long)blockIdx.x * 1024 + threadIdx.x;
#pragma unroll
    for (int k = 0; k < 4; k++) {
        long e = e0 + k * 256;
        if (e >= S6) return;
        const float* s;
        __nv_bfloat16 *d0, *d1;
        long o;
        if (e < S0)      { s = outw; d0 = g_wo0;  d1 = g_wo1;  o = e; }
        else if (e < S1) { s = wih0; d0 = g_wi00; d1 = g_wi01; o = e - S0; }
        else if (e < S2) { s = whh0; d0 = g_wh00; d1 = g_wh01; o = e - S1; }
        else if (e < S3) { s = wih1; d0 = g_wi10; d1 = g_wi11; o = e - S2; }
        else if (e < S4) { s = whh1; d0 = g_wh10; d1 = g_wh11; o = e - S3; }
        else if (e < S5) { s = ipw;  d0 = g_ip0;  d1 = g_ip1;  o = e - S4; }
        else             { s = hid;  d0 = g_hid0; d1 = g_hid1; o = e - S5; }
        float a = s[o];
        __nv_bfloat16 hi = __float2bfloat16(a);
        d0[o] = hi;
        d1[o] = __float2bfloat16(a - __bfloat162float(hi));
    }
}

__global__ void __launch_bounds__(256) k_inproj(void)
{
    GD_TRIGGER();
    int n0 = blockIdx.x * 128;      // 4 tiles over D=512
    int sp = blockIdx.y;            // 16 K-splits of 256
    hgemm_64x128(g_hid0, g_hid1, H_,
                 g_ip0 + (long)n0 * H_, g_ip1 + (long)n0 * H_, H_,
                 g_ipart + (long)sp * (B_ * D_) + n0, (long)D_, sp * 256, 8,
                 2, false, -1, 0);
}

__global__ void __launch_bounds__(256) k_reduce(const float* __restrict__ bias)
{
    GD_TRIGGER();
    GD_WAIT();
    int id = blockIdx.x * 256 + threadIdx.x;   // < 32768
    int d = id & (D_ - 1);
    float s = bias[d];
#pragma unroll
    for (int sp = 0; sp < 16; sp++) s += g_ipart[sp * (B_ * D_) + id];
    g_h0f[id] = s;
    g_h1f[id] = s;
    __nv_bfloat16 hi = __float2bfloat16(s);
    __nv_bfloat16 lo = __float2bfloat16(s - __bfloat162float(hi));
    g_h00[id] = hi; g_h01[id] = lo;
    g_h10[id] = hi; g_h11[id] = lo;
    g_x0[id] = __float2bfloat16(0.f);
    g_x1[id] = __float2bfloat16(0.f);
}

__global__ void __launch_bounds__(256) k_gru(int layer)
{
    GD_TRIGGER();
    int j0 = blockIdx.x * 128;      // 24 tiles over virtual 3072 (gi | gh)
    int sp = blockIdx.y;            // 8 K-splits of 64
    const __nv_bfloat16 *A0, *A1, *W0, *W1;
    if (layer == 0) {
        if (j0 < G3) { A0 = g_x0;  A1 = g_x1;  W0 = g_wi00 + (long)j0 * D_;        W1 = g_wi01 + (long)j0 * D_; }
        else         { A0 = g_h00; A1 = g_h01; W0 = g_wh00 + (long)(j0 - G3) * D_; W1 = g_wh01 + (long)(j0 - G3) * D_; }
    } else {
        if (j0 < G3) { A0 = g_h00; A1 = g_h01; W0 = g_wi10 + (long)j0 * D_;        W1 = g_wi11 + (long)j0 * D_; }
        else         { A0 = g_h10; A1 = g_h11; W0 = g_wh10 + (long)(j0 - G3) * D_; W1 = g_wh11 + (long)(j0 - G3) * D_; }
    }
    hgemm_64x128(A0, A1, D_, W0, W1, D_,
                 g_gP + (long)sp * (B_ * 2 * G3) + j0, (long)(2 * G3), sp * 64, 2,
                 1, false, -1, 0);
}

__global__ void __launch_bounds__(256) k_combine(
    const float* __restrict__ b_ih, const float* __restrict__ b_hh, int layer)
{
    GD_TRIGGER();
    GD_WAIT();
    int id = blockIdx.x * 256 + threadIdx.x;   // < 32768
    int d = id & (D_ - 1);
    long base = (long)(id >> 9) * (2 * G3);
    float s0 = 0.f, s1 = 0.f, s2 = 0.f, s3 = 0.f, s4 = 0.f, s5 = 0.f;
#pragma unroll
    for (int sp = 0; sp < 8; sp++) {
        const float* p = g_gP + (long)sp * (B_ * 2 * G3) + base;
        s0 += p[d];        s1 += p[512 + d];  s2 += p[1024 + d];
        s3 += p[1536 + d]; s4 += p[2048 + d]; s5 += p[2560 + d];
    }
    float r = 1.f / (1.f + expf(-(s0 + b_ih[d] + s3 + b_hh[d])));
    float z = 1.f / (1.f + expf(-(s1 + b_ih[512 + d] + s4 + b_hh[512 + d])));
    float n = tanhf(s2 + b_ih[1024 + d] + r * (s5 + b_hh[1024 + d]));
    float* hf = layer ? g_h1f : g_h0f;
    float hp = hf[id];
    float hn = n + z * (hp - n);
    hf[id] = hn;
    __nv_bfloat16 hi = __float2bfloat16(hn);
    __nv_bfloat16 lo = __float2bfloat16(hn - __bfloat162float(hi));
    if (layer) { g_h10[id] = hi; g_h11[id] = lo; }
    else       { g_h00[id] = hi; g_h01[id] = lo; }
}

__global__ void __launch_bounds__(256) k_logits(float* __restrict__ out, int step,
                                                int do_cand)
{
    GD_TRIGGER();
    int tile = blockIdx.x;
    int n0 = tile * 128;            // 250 tiles over V=32000
    hgemm_64x128(g_h10, g_h11, D_,
                 g_wo0 + (long)n0 * D_, g_wo1 + (long)n0 * D_, D_,
                 out + (long)step * V_ + n0, LDOUT, 0, 16,
                 1, true, do_cand ? tile : -1, n0);
}

__global__ void __launch_bounds__(256) k_select(const float* __restrict__ embed)
{
    GD_TRIGGER();
    GD_WAIT();
    __shared__ float sv[256];
    __shared__ int   si[256];
    int b = blockIdx.x;
    int t = threadIdx.x;
    float bv = -3.4e38f;
    int bi = 0x7FFFFFFF;
    if (t < NTILES_V) { bv = g_candV[t * B_ + b]; bi = g_candI[t * B_ + b]; }
    sv[t] = bv; si[t] = bi;
    __syncthreads();
    for (int s = 128; s > 0; s >>= 1) {
        if (t < s) {
            if (sv[t + s] > sv[t] || (sv[t + s] == sv[t] && si[t + s] < si[t])) {
                sv[t] = sv[t + s]; si[t] = si[t + s];
            }
        }
        __syncthreads();
    }
    int idx = si[0];
    for (int d = t; d < D_; d += 256) {
        float e = embed[(long)idx * D_ + d];
        __nv_bfloat16 hi = __float2bfloat16(e);
        g_x0[b * D_ + d] = hi;
        g_x1[b * D_ + d] = __float2bfloat16(e - __bfloat162float(hi));
    }
}

// ------------------------------ launch --------------------------------------
template <typename F, typename... Args>
static void launch_pdl(F f, dim3 g, dim3 b, size_t smem, Args... args)
{
    cudaLaunchConfig_t cfg = {};
    cfg.gridDim = g;
    cfg.blockDim = b;
    cfg.dynamicSmemBytes = smem;
    cfg.stream = 0;
    cudaLaunchAttribute at[1];
    at[0].id = cudaLaunchAttributeProgrammaticStreamSerialization;
    at[0].val.programmaticStreamSerializationAllowed = 1;
    cfg.attrs = at;
    cfg.numAttrs = 1;
    (void)cudaLaunchKernelEx(&cfg, f, args...);
}

extern "C" void kernel_launch(void* const* d_in, const int* in_sizes, int n_in,
                              void* d_out, int out_size)
{
    const float* hid  = (const float*)d_in[0];
    const float* ipw  = (const float*)d_in[1];
    const float* ipb  = (const float*)d_in[2];
    const float* wih0 = (const float*)d_in[3];
    const float* whh0 = (const float*)d_in[4];
    const float* bih0 = (const float*)d_in[5];
    const float* bhh0 = (const float*)d_in[6];
    const float* bih1 = (const float*)d_in[9];
    const float* wih1 = (const float*)d_in[7];
    const float* whh1 = (const float*)d_in[8];
    const float* bhh1 = (const float*)d_in[10];
    const float* emb  = (const float*)d_in[11];
    const float* outw = (const float*)d_in[12];
    float* out = (float*)d_out;

    (void)cudaFuncSetAttribute(k_inproj, cudaFuncAttributeMaxDynamicSharedMemorySize, DYN_SMEM);
    (void)cudaFuncSetAttribute(k_gru,    cudaFuncAttributeMaxDynamicSharedMemorySize, DYN_SMEM);
    (void)cudaFuncSetAttribute(k_logits, cudaFuncAttributeMaxDynamicSharedMemorySize, DYN_SMEM);

    // split: plain launch (its completion gates all weight prefetches)
    k_split_all<<<(int)((S6 + 1023) / 1024), 256>>>(outw, wih0, whh0, wih1, whh1, ipw, hid);

    launch_pdl(k_inproj, dim3(4, 16), dim3(256), (size_t)DYN_SMEM);
    launch_pdl(k_reduce, dim3(128), dim3(256), (size_t)0, ipb);

    for (int t = 0; t < 4; t++) {
        launch_pdl(k_gru, dim3(24, 8), dim3(256), (size_t)DYN_SMEM, 0);
        launch_pdl(k_combine, dim3(128), dim3(256), (size_t)0, bih0, bhh0, 0);
        launch_pdl(k_gru, dim3(24, 8), dim3(256), (size_t)DYN_SMEM, 1);
        launch_pdl(k_combine, dim3(128), dim3(256), (size_t)0, bih1, bhh1, 1);
        launch_pdl(k_logits, dim3(NTILES_V), dim3(256), (size_t)DYN_SMEM,
                   out, t, t < 3 ? 1 : 0);
        if (t < 3) launch_pdl(k_select, dim3(64), dim3(256), (size_t)0, emb);
    }
}